// round 13
// baseline (speedup 1.0000x reference)
#include <cuda_runtime.h>
#include <cstdint>
#include <cstddef>
#include <cstdio>

// Problem: B=64, T=2048, D=512, H=512
#define NCTA 128      // 16 column-groups x 8 batch-groups
#define NTHR 256
#define WPAD 516      // padded SMEM row stride (516 % 32 == 4 -> conflict-free)
#define CLUSZ 16      // CTAs per cluster (one full column span)

// ---------------- static device scratch (no runtime allocation) ----------------
__device__ float g_xzr[64ull * 2048 * 1024];  // [B,T,2H] input zr projection
__device__ float g_xo [64ull * 2048 * 512];   // [B,T,H]  input o  projection
__device__ float g_h  [64 * 512];             // (fallback path) hidden state
__device__ float g_rg [64 * 512];             // (fallback path) h*sigmoid(r)
__device__ int   g_cnt   = 0;
__device__ int   g_sense = 0;

// ---------------- f32x2 packed-FMA helpers (PTX-only on sm_103a) ----------------
__device__ __forceinline__ void fma2(unsigned long long& d,
                                     unsigned long long a, unsigned long long b) {
    asm("fma.rn.f32x2 %0, %1, %2, %0;" : "+l"(d) : "l"(a), "l"(b));
}
__device__ __forceinline__ unsigned long long pk(float lo, float hi) {
    unsigned long long r;
    asm("mov.b64 %0, {%1, %2};" : "=l"(r) : "f"(lo), "f"(hi));
    return r;
}
__device__ __forceinline__ float2 upk(unsigned long long v) {
    float2 f;
    asm("mov.b64 {%0, %1}, %2;" : "=f"(f.x), "=f"(f.y) : "l"(v));
    return f;
}

// ---------------------------------------------------------------------------
// Kernel 1: fused input-projection SGEMM (f32x2 packed over k-pairs)
// ---------------------------------------------------------------------------
__global__ __launch_bounds__(256) void proj_gemm(
    const float* __restrict__ A,
    const float* __restrict__ Wih, const float* __restrict__ bih,
    const float* __restrict__ Wio, const float* __restrict__ bio)
{
    __shared__ __align__(16) float As[16][132];  // [k][m]
    __shared__ __align__(16) float Bs[16][68];   // [k][n]

    const int tid = threadIdx.x;
    const int n0  = blockIdx.x * 64;
    const size_t m0 = (size_t)blockIdx.y * 128;

    const float* W; const float* bias; float* out; int ldo; int nc0;
    if (n0 < 1024) { W = Wih; bias = bih; out = g_xzr; ldo = 1024; nc0 = n0; }
    else           { W = Wio; bias = bio; out = g_xo;  ldo = 512;  nc0 = n0 - 1024; }

    const int ar  = tid >> 2;
    const int ac4 = tid & 3;
    const int ty  = tid >> 4;
    const int tx  = tid & 15;

    unsigned long long acc[8][4];
#pragma unroll
    for (int i = 0; i < 8; i++)
#pragma unroll
        for (int j = 0; j < 4; j++) acc[i][j] = 0ull;

    float4 pa0 = *(const float4*)(A + (m0 + ar) * 512 + ac4 * 4);
    float4 pa1 = *(const float4*)(A + (m0 + 64 + ar) * 512 + ac4 * 4);
    float4 pb  = *(const float4*)(W + (size_t)(nc0 + ar) * 512 + ac4 * 4);

    for (int k0 = 0; k0 < 512; k0 += 16) {
        As[ac4*4+0][ar]      = pa0.x; As[ac4*4+1][ar]      = pa0.y;
        As[ac4*4+2][ar]      = pa0.z; As[ac4*4+3][ar]      = pa0.w;
        As[ac4*4+0][64 + ar] = pa1.x; As[ac4*4+1][64 + ar] = pa1.y;
        As[ac4*4+2][64 + ar] = pa1.z; As[ac4*4+3][64 + ar] = pa1.w;
        Bs[ac4*4+0][ar] = pb.x; Bs[ac4*4+1][ar] = pb.y;
        Bs[ac4*4+2][ar] = pb.z; Bs[ac4*4+3][ar] = pb.w;
        __syncthreads();

        if (k0 + 16 < 512) {
            pa0 = *(const float4*)(A + (m0 + ar) * 512 + k0 + 16 + ac4 * 4);
            pa1 = *(const float4*)(A + (m0 + 64 + ar) * 512 + k0 + 16 + ac4 * 4);
            pb  = *(const float4*)(W + (size_t)(nc0 + ar) * 512 + k0 + 16 + ac4 * 4);
        }

#pragma unroll
        for (int kp = 0; kp < 8; kp++) {
            const int kk = kp * 2;
            float4 al0 = *(const float4*)&As[kk][ty * 8];
            float4 al1 = *(const float4*)&As[kk][ty * 8 + 4];
            float4 ah0 = *(const float4*)&As[kk + 1][ty * 8];
            float4 ah1 = *(const float4*)&As[kk + 1][ty * 8 + 4];
            float4 bl  = *(const float4*)&Bs[kk][tx * 4];
            float4 bh  = *(const float4*)&Bs[kk + 1][tx * 4];
            unsigned long long pbv[4] = {
                pk(bl.x, bh.x), pk(bl.y, bh.y), pk(bl.z, bh.z), pk(bl.w, bh.w) };
            float alv[8] = {al0.x, al0.y, al0.z, al0.w, al1.x, al1.y, al1.z, al1.w};
            float ahv[8] = {ah0.x, ah0.y, ah0.z, ah0.w, ah1.x, ah1.y, ah1.z, ah1.w};
#pragma unroll
            for (int i = 0; i < 8; i++) {
                unsigned long long pav = pk(alv[i], ahv[i]);
                fma2(acc[i][0], pav, pbv[0]);
                fma2(acc[i][1], pav, pbv[1]);
                fma2(acc[i][2], pav, pbv[2]);
                fma2(acc[i][3], pav, pbv[3]);
            }
        }
        __syncthreads();
    }

    float4 bv4 = *(const float4*)(bias + nc0 + tx * 4);
#pragma unroll
    for (int i = 0; i < 8; i++) {
        float2 c0 = upk(acc[i][0]), c1 = upk(acc[i][1]);
        float2 c2 = upk(acc[i][2]), c3 = upk(acc[i][3]);
        float4 v;
        v.x = c0.x + c0.y + bv4.x; v.y = c1.x + c1.y + bv4.y;
        v.z = c2.x + c2.y + bv4.z; v.w = c3.x + c3.y + bv4.w;
        *(float4*)(out + (m0 + ty * 8 + i) * ldo + nc0 + tx * 4) = v;
    }
}

// ===========================================================================
// Cluster-based recurrence: 8 clusters x 16 CTAs. Cluster owns 8 batch rows
// end-to-end; CTA rank r owns columns [32r, 32r+32). h / rg exchanged via
// DSMEM multicast + barrier.cluster. NO grid barrier, NO L2 state traffic.
// ===========================================================================
__device__ __forceinline__ void cluster_sync_() {
    asm volatile("barrier.cluster.arrive.aligned;" ::: "memory");
    asm volatile("barrier.cluster.wait.aligned;"   ::: "memory");
}

// broadcast local 8x32 block (blk, row-major stride 32) into every cluster
// CTA's buffer at column offset rank*32 (dst rows stride WPAD)
__device__ __forceinline__ void bcast_blk(const float* __restrict__ blk,
                                          float* dstbase, int rank)
{
    unsigned base = (unsigned)__cvta_generic_to_shared(dstbase) + rank * 32 * 4;
#pragma unroll
    for (int it = 0; it < 4; it++) {
        int task = threadIdx.x + it * NTHR;     // 0..1023
        int peer = task >> 6;                   // 0..15
        int vec  = task & 63;                   // 8 rows x 8 float4
        int row  = vec >> 3, q4 = vec & 7;
        float4 v = *(const float4*)(blk + vec * 4);
        unsigned la = base + row * WPAD * 4 + q4 * 16;
        unsigned ra;
        asm("mapa.shared::cluster.u32 %0, %1, %2;" : "=r"(ra) : "r"(la), "r"(peer));
        asm volatile("st.shared::cluster.v4.f32 [%0], {%1,%2,%3,%4};"
                     :: "r"(ra), "f"(v.x), "f"(v.y), "f"(v.z), "f"(v.w) : "memory");
    }
}

__global__ __launch_bounds__(NTHR, 1) void gru_clu(
    const int*   __restrict__ lens,
    const float* __restrict__ Whh, const float* __restrict__ bhh,
    const float* __restrict__ Who, const float* __restrict__ bho,
    float* __restrict__ out)
{
    extern __shared__ float sm[];
    float* Wz  = sm;                    // [32][WPAD]
    float* Wr  = sm + 32 * WPAD;
    float* Wo  = sm + 64 * WPAD;
    float* hb  = sm + 96 * WPAD;        // [8][WPAD] full-width h for my 8 rows
    float* rgb = sm + 104 * WPAD;       // [8][WPAD] full-width rg
    float* blk = sm + 112 * WPAD;       // [256] local 8x32 block scratch

    const int tid  = threadIdx.x;
    const int w    = tid >> 5;
    const int lane = tid & 31;
    unsigned rank;
    asm("mov.u32 %0, %%cluster_ctarank;" : "=r"(rank));
    const int c       = blockIdx.x >> 4;        // batch group 0..7
    const int j_local = w * 4 + (lane & 3);     // 0..31
    const int b_local = lane >> 2;              // 0..7
    const int jg = (int)rank * 32 + j_local;
    const int b  = c * 8 + b_local;

    // stage weight slices once (reused across all 2048 steps)
    for (int idx = tid; idx < 32 * 128; idx += NTHR) {
        int jj = idx >> 7, q = idx & 127;
        *(float4*)&Wz[jj * WPAD + q * 4] =
            *(const float4*)&Whh[(size_t)((int)rank * 32 + jj) * 512 + q * 4];
        *(float4*)&Wr[jj * WPAD + q * 4] =
            *(const float4*)&Whh[(size_t)(512 + (int)rank * 32 + jj) * 512 + q * 4];
        *(float4*)&Wo[jj * WPAD + q * 4] =
            *(const float4*)&Who[(size_t)((int)rank * 32 + jj) * 512 + q * 4];
    }
    // zero my h buffer (h0 = 0); peers only write it after the first barrier
    for (int idx = tid; idx < 1024; idx += NTHR) {
        int row = idx >> 7, q = idx & 127;
        *(float4*)&hb[row * WPAD + q * 4] = make_float4(0.f, 0.f, 0.f, 0.f);
    }

    const float bz = bhh[jg], br = bhh[512 + jg], bo = bho[jg];
    const int   lb = lens[b];
    float myh = 0.f;
    __syncthreads();

    float* outF = out + 64ull * 2048 * 512;

    const ulonglong2* zv = (const ulonglong2*)(Wz + j_local * WPAD);
    const ulonglong2* rv = (const ulonglong2*)(Wr + j_local * WPAD);
    const ulonglong2* ov = (const ulonglong2*)(Wo + j_local * WPAD);
    const ulonglong2* hv = (const ulonglong2*)(hb  + b_local * WPAD);
    const ulonglong2* gv = (const ulonglong2*)(rgb + b_local * WPAD);

    unsigned long long cycA = 0, cycXA = 0, cycB = 0, cycXB = 0;
    long long t0 = clock64(), t1;

    for (int t = 0; t < 2048; t++) {
        // ---------------- phase A: z/r preacts from local hb ----------------
        const size_t rowzr = ((size_t)b * 2048 + t) * 1024;
        const float xz = g_xzr[rowzr + jg];
        const float xr = g_xzr[rowzr + 512 + jg];
        const float xo = g_xo[((size_t)b * 2048 + t) * 512 + jg];

        unsigned long long az0 = 0, az1 = 0, ar0 = 0, ar1 = 0;
#pragma unroll 8
        for (int q = 0; q < 128; q++) {
            ulonglong2 h2 = hv[q], z2 = zv[q], r2 = rv[q];
            fma2(az0, h2.x, z2.x); fma2(az1, h2.y, z2.y);
            fma2(ar0, h2.x, r2.x); fma2(ar1, h2.y, r2.y);
        }
        float2 z0 = upk(az0), z1 = upk(az1), r0 = upk(ar0), r1 = upk(ar1);
        float az = bz + xz + z0.x + z0.y + z1.x + z1.y;
        float ar = br + xr + r0.x + r0.y + r1.x + r1.y;
        float sr = 1.f / (1.f + expf(-ar));
        blk[b_local * 32 + j_local] = myh * sr;
        float zs = 1.f / (1.f + expf(-az));
        __syncthreads();
        t1 = clock64(); cycA += (unsigned long long)(t1 - t0); t0 = t1;

        // ------------- exchange A: rg block -> every CTA's rgb --------------
        bcast_blk(blk, rgb, (int)rank);
        cluster_sync_();
        t1 = clock64(); cycXA += (unsigned long long)(t1 - t0); t0 = t1;

        // ---------------- phase B: s preact, state update -------------------
        unsigned long long ao0 = 0, ao1 = 0;
#pragma unroll 8
        for (int q = 0; q < 128; q++) {
            ulonglong2 h2 = gv[q], o2 = ov[q];
            fma2(ao0, h2.x, o2.x); fma2(ao1, h2.y, o2.y);
        }
        float2 o0 = upk(ao0), o1 = upk(ao1);
        float as_ = bo + xo + o0.x + o0.y + o1.x + o1.y;

        float hn  = (1.f - zs) * myh + zs * tanhf(as_);
        bool  act = (t < lb);
        out[((size_t)b * 2048 + t) * 512 + jg] = act ? hn : 0.f;
        if (act) myh = hn;
        blk[b_local * 32 + j_local] = myh;
        __syncthreads();
        t1 = clock64(); cycB += (unsigned long long)(t1 - t0); t0 = t1;

        // ------------- exchange B: new h block -> every CTA's hb ------------
        bcast_blk(blk, hb, (int)rank);
        cluster_sync_();
        t1 = clock64(); cycXB += (unsigned long long)(t1 - t0); t0 = t1;
    }

    outF[b * 512 + jg] = myh;

    if (blockIdx.x == 0 && tid == 0)
        printf("CYCBRK A=%llu XA=%llu B=%llu XB=%llu\n", cycA, cycXA, cycB, cycXB);
}

// ===========================================================================
// Fallback (proven R12 path): grid-barrier persistent kernel
// ===========================================================================
__device__ __forceinline__ void st_rel(float* p, float v) {
    asm volatile("st.relaxed.gpu.global.f32 [%0], %1;" :: "l"(p), "f"(v));
}
__device__ __forceinline__ void stage8(const float* __restrict__ src,
                                       float* dst, int b0, int kbase)
{
    const int t = threadIdx.x;
#pragma unroll
    for (int i = 0; i < 2; i++) {
        int idx = t + i * NTHR;
        int r   = idx >> 6;
        int q   = idx & 63;
        const float* s = src + (size_t)(b0 + r) * 512 + kbase + q * 4;
        float*       d = dst + r * WPAD + kbase + q * 4;
        unsigned sa = (unsigned)__cvta_generic_to_shared(d);
        asm volatile("cp.async.cg.shared.global [%0], [%1], 16;"
                     :: "r"(sa), "l"(s));
    }
}
__device__ __forceinline__ void gbar(int& snc) {
    __syncthreads();
    snc ^= 1;
    if (threadIdx.x == 0) {
        int old;
        asm volatile("atom.acq_rel.gpu.global.add.s32 %0, [%1], 1;"
                     : "=r"(old) : "l"(&g_cnt) : "memory");
        if (old == NCTA - 1) {
            asm volatile("st.relaxed.gpu.global.s32 [%0], 0;"
                         :: "l"(&g_cnt) : "memory");
            asm volatile("st.release.gpu.global.s32 [%0], %1;"
                         :: "l"(&g_sense), "r"(snc) : "memory");
        }
    }
    if (threadIdx.x < 32) {
        int cur;
        do {
            asm volatile("ld.acquire.gpu.global.s32 %0, [%1];"
                         : "=r"(cur) : "l"(&g_sense) : "memory");
        } while (cur != snc);
    }
    __syncthreads();
}

__global__ __launch_bounds__(NTHR, 1) void gru_rec(
    const int*   __restrict__ lens,
    const float* __restrict__ Whh, const float* __restrict__ bhh,
    const float* __restrict__ Who, const float* __restrict__ bho,
    float* __restrict__ out)
{
    extern __shared__ float sm[];
    float* Wz = sm;
    float* Wr = sm + 32 * WPAD;
    float* Wo = sm + 64 * WPAD;
    float* hb = sm + 96 * WPAD;

    const int tid  = threadIdx.x;
    const int w    = tid >> 5;
    const int lane = tid & 31;
    const int cg   = blockIdx.x >> 3;
    const int bg   = blockIdx.x & 7;
    const int j_local = w * 4 + (lane & 3);
    const int b_local = lane >> 2;
    const int jg = cg * 32 + j_local;
    const int b0 = bg * 8;
    const int b  = b0 + b_local;

    int snc;
    asm volatile("ld.acquire.gpu.global.s32 %0, [%1];"
                 : "=r"(snc) : "l"(&g_sense) : "memory");

    for (int idx = tid; idx < 32 * 128; idx += NTHR) {
        int jj = idx >> 7, q = idx & 127;
        *(float4*)&Wz[jj * WPAD + q * 4] =
            *(const float4*)&Whh[(size_t)(cg * 32 + jj) * 512 + q * 4];
        *(float4*)&Wr[jj * WPAD + q * 4] =
            *(const float4*)&Whh[(size_t)(512 + cg * 32 + jj) * 512 + q * 4];
        *(float4*)&Wo[jj * WPAD + q * 4] =
            *(const float4*)&Who[(size_t)(cg * 32 + jj) * 512 + q * 4];
    }

    const float bz = bhh[jg], br = bhh[512 + jg], bo = bho[jg];
    const int   lb = lens[b];
    float myh = 0.f;
    st_rel(&g_h[b * 512 + jg], 0.f);
    gbar(snc);

    float* outF = out + 64ull * 2048 * 512;

    const ulonglong2* zv = (const ulonglong2*)(Wz + j_local * WPAD);
    const ulonglong2* rv = (const ulonglong2*)(Wr + j_local * WPAD);
    const ulonglong2* ov = (const ulonglong2*)(Wo + j_local * WPAD);
    const ulonglong2* hv = (const ulonglong2*)(hb + b_local * WPAD);

    for (int t = 0; t < 2048; t++) {
        stage8(g_h, hb, b0, 0);   asm volatile("cp.async.commit_group;");
        stage8(g_h, hb, b0, 256); asm volatile("cp.async.commit_group;");

        const size_t rowzr = ((size_t)b * 2048 + t) * 1024;
        const float xz = g_xzr[rowzr + jg];
        const float xr = g_xzr[rowzr + 512 + jg];

        unsigned long long az0 = 0, az1 = 0, ar0 = 0, ar1 = 0;
        asm volatile("cp.async.wait_group 1;");
        __syncthreads();
#pragma unroll 8
        for (int q = 0; q < 64; q++) {
            ulonglong2 h2 = hv[q], z2 = zv[q], r2 = rv[q];
            fma2(az0, h2.x, z2.x); fma2(az1, h2.y, z2.y);
            fma2(ar0, h2.x, r2.x); fma2(ar1, h2.y, r2.y);
        }
        asm volatile("cp.async.wait_group 0;");
        __syncthreads();
#pragma unroll 8
        for (int q = 64; q < 128; q++) {
            ulonglong2 h2 = hv[q], z2 = zv[q], r2 = rv[q];
            fma2(az0, h2.x, z2.x); fma2(az1, h2.y, z2.y);
            fma2(ar0, h2.x, r2.x); fma2(ar1, h2.y, r2.y);
        }
        float2 z0 = upk(az0), z1 = upk(az1), r0 = upk(ar0), r1 = upk(ar1);
        float az = bz + xz + z0.x + z0.y + z1.x + z1.y;
        float ar = br + xr + r0.x + r0.y + r1.x + r1.y;
        float sr = 1.f / (1.f + expf(-ar));
        st_rel(&g_rg[b * 512 + jg], myh * sr);
        float zs = 1.f / (1.f + expf(-az));
        gbar(snc);

        stage8(g_rg, hb, b0, 0);   asm volatile("cp.async.commit_group;");
        stage8(g_rg, hb, b0, 256); asm volatile("cp.async.commit_group;");

        const float xo = g_xo[((size_t)b * 2048 + t) * 512 + jg];
        unsigned long long ao0 = 0, ao1 = 0;
        asm volatile("cp.async.wait_group 1;");
        __syncthreads();
#pragma unroll 8
        for (int q = 0; q < 64; q++) {
            ulonglong2 h2 = hv[q], o2 = ov[q];
            fma2(ao0, h2.x, o2.x); fma2(ao1, h2.y, o2.y);
        }
        asm volatile("cp.async.wait_group 0;");
        __syncthreads();
#pragma unroll 8
        for (int q = 64; q < 128; q++) {
            ulonglong2 h2 = hv[q], o2 = ov[q];
            fma2(ao0, h2.x, o2.x); fma2(ao1, h2.y, o2.y);
        }
        float2 o0 = upk(ao0), o1 = upk(ao1);
        float as_ = bo + xo + o0.x + o0.y + o1.x + o1.y;

        float hn  = (1.f - zs) * myh + zs * tanhf(as_);
        bool  act = (t < lb);
        out[((size_t)b * 2048 + t) * 512 + jg] = act ? hn : 0.f;
        if (act) myh = hn;
        st_rel(&g_h[b * 512 + jg], myh);
        gbar(snc);
    }

    outF[b * 512 + jg] = myh;
}

// ---------------------------------------------------------------------------
extern "C" void kernel_launch(void* const* d_in, const int* in_sizes, int n_in,
                              void* d_out, int out_size)
{
    const float* seq  = (const float*)d_in[0];
    const int*   lens = (const int*)  d_in[1];
    const float* Wih  = (const float*)d_in[2];
    const float* bih  = (const float*)d_in[3];
    const float* Whh  = (const float*)d_in[4];
    const float* bhh  = (const float*)d_in[5];
    const float* Wio  = (const float*)d_in[6];
    const float* bio  = (const float*)d_in[7];
    const float* Who  = (const float*)d_in[8];
    const float* bho  = (const float*)d_in[9];
    float* out = (float*)d_out;

    const int smem_clu = (112 * WPAD + 256) * (int)sizeof(float);  // 232,192 B
    const int smem_rec = (104 * WPAD) * (int)sizeof(float);        // 214,656 B

    // one-time capability probe (result identical every call -> deterministic)
    static int use_cluster = -1;
    if (use_cluster < 0) {
        cudaError_t e1 = cudaFuncSetAttribute(
            gru_clu, cudaFuncAttributeNonPortableClusterSizeAllowed, 1);
        cudaError_t e2 = cudaFuncSetAttribute(
            gru_clu, cudaFuncAttributeMaxDynamicSharedMemorySize, smem_clu);
        int maxc = 0;
        cudaLaunchConfig_t qcfg = {};
        qcfg.gridDim = dim3(NCTA); qcfg.blockDim = dim3(NTHR);
        qcfg.dynamicSmemBytes = smem_clu;
        cudaError_t e3 = cudaOccupancyMaxPotentialClusterSize(&maxc, gru_clu, &qcfg);
        use_cluster = (e1 == cudaSuccess && e2 == cudaSuccess &&
                       e3 == cudaSuccess && maxc >= CLUSZ) ? 1 : 0;
        if (!use_cluster)
            cudaFuncSetAttribute(gru_rec,
                cudaFuncAttributeMaxDynamicSharedMemorySize, smem_rec);
        cudaGetLastError();   // clear any sticky error from probing
    }

    dim3 grid(24, 1024);
    proj_gemm<<<grid, 256>>>(seq, Wih, bih, Wio, bio);

    if (use_cluster) {
        cudaLaunchConfig_t cfg = {};
        cfg.gridDim = dim3(NCTA); cfg.blockDim = dim3(NTHR);
        cfg.dynamicSmemBytes = smem_clu;
        cfg.stream = 0;
        cudaLaunchAttribute attrs[1];
        attrs[0].id = cudaLaunchAttributeClusterDimension;
        attrs[0].val.clusterDim = {CLUSZ, 1, 1};
        cfg.attrs = attrs; cfg.numAttrs = 1;
        cudaLaunchKernelEx(&cfg, gru_clu, lens, Whh, bhh, Who, bho, out);
    } else {
        gru_rec<<<NCTA, NTHR, smem_rec>>>(lens, Whh, bhh, Who, bho, out);
    }
}

// round 14
// speedup vs baseline: 1.3107x; 1.3107x over previous
#include <cuda_runtime.h>
#include <cstdint>
#include <cstddef>

// Problem: B=64, T=2048, D=512, H=512
#define NCTA 128      // 16 column-groups x 8 batch-groups
#define NTHR 256
#define WPAD 516      // padded SMEM row stride (516 % 32 == 4 -> conflict-free)

// ---------------- static device scratch (no runtime allocation) ----------------
__device__ float g_xzr[64ull * 2048 * 1024];  // [B,T,2H] input zr projection
__device__ float g_xo [64ull * 2048 * 512];   // [B,T,H]  input o  projection
__device__ float g_h  [64 * 512];             // current hidden state
__device__ float g_rg [64 * 512];             // h * sigmoid(r)
__device__ int   g_cnt   = 0;                 // init barrier only
__device__ int   g_sense = 0;                 // init barrier only
__device__ int   g_flagA[NCTA];               // monotonic per-CTA phase-A flags
__device__ int   g_flagB[NCTA];               // monotonic per-CTA phase-B flags

// ---------------- f32x2 packed-FMA helpers (PTX-only on sm_103a) ----------------
__device__ __forceinline__ void fma2(unsigned long long& d,
                                     unsigned long long a, unsigned long long b) {
    asm("fma.rn.f32x2 %0, %1, %2, %0;" : "+l"(d) : "l"(a), "l"(b));
}
__device__ __forceinline__ unsigned long long pk(float lo, float hi) {
    unsigned long long r;
    asm("mov.b64 %0, {%1, %2};" : "=l"(r) : "f"(lo), "f"(hi));
    return r;
}
__device__ __forceinline__ float2 upk(unsigned long long v) {
    float2 f;
    asm("mov.b64 {%0, %1}, %2;" : "=f"(f.x), "=f"(f.y) : "l"(v));
    return f;
}

// ---------------------------------------------------------------------------
// Kernel 1: fused input-projection SGEMM (f32x2 packed over k-pairs)
//   n in [0,1024):    g_xzr[m,n] = seq[m,:] . W_i2h[n,:] + b_i2h[n]
//   n in [1024,1536): g_xo [m,n-1024] likewise with W_i2o/b_i2o
// ---------------------------------------------------------------------------
__global__ __launch_bounds__(256) void proj_gemm(
    const float* __restrict__ A,
    const float* __restrict__ Wih, const float* __restrict__ bih,
    const float* __restrict__ Wio, const float* __restrict__ bio)
{
    __shared__ __align__(16) float As[16][132];  // [k][m]
    __shared__ __align__(16) float Bs[16][68];   // [k][n]

    const int tid = threadIdx.x;
    const int n0  = blockIdx.x * 64;
    const size_t m0 = (size_t)blockIdx.y * 128;

    const float* W; const float* bias; float* out; int ldo; int nc0;
    if (n0 < 1024) { W = Wih; bias = bih; out = g_xzr; ldo = 1024; nc0 = n0; }
    else           { W = Wio; bias = bio; out = g_xo;  ldo = 512;  nc0 = n0 - 1024; }

    const int ar  = tid >> 2;
    const int ac4 = tid & 3;
    const int ty  = tid >> 4;
    const int tx  = tid & 15;

    unsigned long long acc[8][4];
#pragma unroll
    for (int i = 0; i < 8; i++)
#pragma unroll
        for (int j = 0; j < 4; j++) acc[i][j] = 0ull;

    float4 pa0 = *(const float4*)(A + (m0 + ar) * 512 + ac4 * 4);
    float4 pa1 = *(const float4*)(A + (m0 + 64 + ar) * 512 + ac4 * 4);
    float4 pb  = *(const float4*)(W + (size_t)(nc0 + ar) * 512 + ac4 * 4);

    for (int k0 = 0; k0 < 512; k0 += 16) {
        As[ac4*4+0][ar]      = pa0.x; As[ac4*4+1][ar]      = pa0.y;
        As[ac4*4+2][ar]      = pa0.z; As[ac4*4+3][ar]      = pa0.w;
        As[ac4*4+0][64 + ar] = pa1.x; As[ac4*4+1][64 + ar] = pa1.y;
        As[ac4*4+2][64 + ar] = pa1.z; As[ac4*4+3][64 + ar] = pa1.w;
        Bs[ac4*4+0][ar] = pb.x; Bs[ac4*4+1][ar] = pb.y;
        Bs[ac4*4+2][ar] = pb.z; Bs[ac4*4+3][ar] = pb.w;
        __syncthreads();

        if (k0 + 16 < 512) {
            pa0 = *(const float4*)(A + (m0 + ar) * 512 + k0 + 16 + ac4 * 4);
            pa1 = *(const float4*)(A + (m0 + 64 + ar) * 512 + k0 + 16 + ac4 * 4);
            pb  = *(const float4*)(W + (size_t)(nc0 + ar) * 512 + k0 + 16 + ac4 * 4);
        }

#pragma unroll
        for (int kp = 0; kp < 8; kp++) {
            const int kk = kp * 2;
            float4 al0 = *(const float4*)&As[kk][ty * 8];
            float4 al1 = *(const float4*)&As[kk][ty * 8 + 4];
            float4 ah0 = *(const float4*)&As[kk + 1][ty * 8];
            float4 ah1 = *(const float4*)&As[kk + 1][ty * 8 + 4];
            float4 bl  = *(const float4*)&Bs[kk][tx * 4];
            float4 bh  = *(const float4*)&Bs[kk + 1][tx * 4];
            unsigned long long pbv[4] = {
                pk(bl.x, bh.x), pk(bl.y, bh.y), pk(bl.z, bh.z), pk(bl.w, bh.w) };
            float alv[8] = {al0.x, al0.y, al0.z, al0.w, al1.x, al1.y, al1.z, al1.w};
            float ahv[8] = {ah0.x, ah0.y, ah0.z, ah0.w, ah1.x, ah1.y, ah1.z, ah1.w};
#pragma unroll
            for (int i = 0; i < 8; i++) {
                unsigned long long pav = pk(alv[i], ahv[i]);
                fma2(acc[i][0], pav, pbv[0]);
                fma2(acc[i][1], pav, pbv[1]);
                fma2(acc[i][2], pav, pbv[2]);
                fma2(acc[i][3], pav, pbv[3]);
            }
        }
        __syncthreads();
    }

    float4 bv4 = *(const float4*)(bias + nc0 + tx * 4);
#pragma unroll
    for (int i = 0; i < 8; i++) {
        float2 c0 = upk(acc[i][0]), c1 = upk(acc[i][1]);
        float2 c2 = upk(acc[i][2]), c3 = upk(acc[i][3]);
        float4 v;
        v.x = c0.x + c0.y + bv4.x; v.y = c1.x + c1.y + bv4.y;
        v.z = c2.x + c2.y + bv4.z; v.w = c3.x + c3.y + bv4.w;
        *(float4*)(out + (m0 + ty * 8 + i) * ldo + nc0 + tx * 4) = v;
    }
}

// ---------------------------------------------------------------------------
// Persistent recurrence kernel: 128 CTAs = 16 col-groups x 8 batch-groups.
// Sync scope = the 16 CTAs of one batch group, via per-CTA monotonic flags.
// ---------------------------------------------------------------------------
__device__ __forceinline__ void st_rel(float* p, float v) {
    asm volatile("st.relaxed.gpu.global.f32 [%0], %1;" :: "l"(p), "f"(v));
}

// stage rows [b0, b0+8), cols [kbase, kbase+256) of src[64][512] -> dst[8][WPAD]
__device__ __forceinline__ void stage8(const float* __restrict__ src,
                                       float* dst, int b0, int kbase)
{
    const int t = threadIdx.x;
#pragma unroll
    for (int i = 0; i < 2; i++) {
        int idx = t + i * NTHR;
        int r   = idx >> 6;
        int q   = idx & 63;
        const float* s = src + (size_t)(b0 + r) * 512 + kbase + q * 4;
        float*       d = dst + r * WPAD + kbase + q * 4;
        unsigned sa = (unsigned)__cvta_generic_to_shared(d);
        asm volatile("cp.async.cg.shared.global [%0], [%1], 16;"
                     :: "r"(sa), "l"(s));
    }
}

// one-time grid-wide init barrier (counter-based; only runs once per launch)
__device__ __forceinline__ void init_bar(int& snc) {
    __syncthreads();
    snc ^= 1;
    if (threadIdx.x == 0) {
        int old;
        asm volatile("atom.acq_rel.gpu.global.add.s32 %0, [%1], 1;"
                     : "=r"(old) : "l"(&g_cnt) : "memory");
        if (old == NCTA - 1) {
            asm volatile("st.relaxed.gpu.global.s32 [%0], 0;"
                         :: "l"(&g_cnt) : "memory");
            asm volatile("st.release.gpu.global.s32 [%0], %1;"
                         :: "l"(&g_sense), "r"(snc) : "memory");
        }
    }
    if (threadIdx.x < 32) {
        int cur;
        do {
            asm volatile("ld.acquire.gpu.global.s32 %0, [%1];"
                         : "=r"(cur) : "l"(&g_sense) : "memory");
        } while (cur != snc);
    }
    __syncthreads();
}

// publish my flag (release) after a CTA-wide syncthreads
__device__ __forceinline__ void set_flag(int* slot, int val) {
    __syncthreads();                  // all this CTA's st.relaxed.gpu done
    if (threadIdx.x == 0)
        asm volatile("st.release.gpu.global.s32 [%0], %1;"
                     :: "l"(slot), "r"(val) : "memory");
}

// wait until all 16 flags of my batch group reach tgt (16 parallel pollers)
__device__ __forceinline__ void group_wait(const int* flags, int base, int tgt) {
    if (threadIdx.x < 32) {
        const int lane = threadIdx.x;
        const int* p = flags + base + ((lane < 16) ? lane : 0);
        bool done;
        do {
            int v;
            asm volatile("ld.acquire.gpu.global.s32 %0, [%1];"
                         : "=r"(v) : "l"(p) : "memory");
            done = __all_sync(0xffffffffu, (lane >= 16) || (v >= tgt));
        } while (!done);
    }
    __syncthreads();
}

__global__ __launch_bounds__(NTHR, 1) void gru_rec(
    const int*   __restrict__ lens,
    const float* __restrict__ Whh, const float* __restrict__ bhh,
    const float* __restrict__ Who, const float* __restrict__ bho,
    float* __restrict__ out)
{
    extern __shared__ float sm[];
    float* Wz = sm;                  // [32][WPAD]
    float* Wr = sm + 32 * WPAD;
    float* Wo = sm + 64 * WPAD;
    float* hb = sm + 96 * WPAD;      // [8][WPAD] staging (h or rg)

    const int tid  = threadIdx.x;
    const int w    = tid >> 5;
    const int lane = tid & 31;
    const int cg   = blockIdx.x >> 3;       // 0..15 column group
    const int bg   = blockIdx.x & 7;        // 0..7  batch group
    const int me   = bg * 16 + cg;          // my flag slot
    const int fb   = bg * 16;               // my group's flag base
    const int j_local = w * 4 + (lane & 3);
    const int b_local = lane >> 2;
    const int jg = cg * 32 + j_local;
    const int b0 = bg * 8;
    const int b  = b0 + b_local;

    int snc;
    asm volatile("ld.acquire.gpu.global.s32 %0, [%1];"
                 : "=r"(snc) : "l"(&g_sense) : "memory");

    // stage weight slices once (reused across all 2048 steps)
    for (int idx = tid; idx < 32 * 128; idx += NTHR) {
        int jj = idx >> 7, q = idx & 127;
        *(float4*)&Wz[jj * WPAD + q * 4] =
            *(const float4*)&Whh[(size_t)(cg * 32 + jj) * 512 + q * 4];
        *(float4*)&Wr[jj * WPAD + q * 4] =
            *(const float4*)&Whh[(size_t)(512 + cg * 32 + jj) * 512 + q * 4];
        *(float4*)&Wo[jj * WPAD + q * 4] =
            *(const float4*)&Who[(size_t)(cg * 32 + jj) * 512 + q * 4];
    }

    const float bz = bhh[jg], br = bhh[512 + jg], bo = bho[jg];
    const int   lb = lens[b];
    float myh = 0.f;

    // reset state + my flags, then one grid-wide init barrier (replay-safe)
    st_rel(&g_h[b * 512 + jg], 0.f);
    if (tid == 0) {
        asm volatile("st.relaxed.gpu.global.s32 [%0], 0;"
                     :: "l"(&g_flagA[me]) : "memory");
        asm volatile("st.relaxed.gpu.global.s32 [%0], 0;"
                     :: "l"(&g_flagB[me]) : "memory");
    }
    init_bar(snc);

    float* outF = out + 64ull * 2048 * 512;   // final_state region

    const ulonglong2* zv = (const ulonglong2*)(Wz + j_local * WPAD);
    const ulonglong2* rv = (const ulonglong2*)(Wr + j_local * WPAD);
    const ulonglong2* ov = (const ulonglong2*)(Wo + j_local * WPAD);
    const ulonglong2* hv = (const ulonglong2*)(hb + b_local * WPAD);

    // prefetch step-0 input projections
    size_t rowzr = ((size_t)b * 2048) * 1024;
    size_t rowo  = ((size_t)b * 2048) * 512;
    float xz = g_xzr[rowzr + jg];
    float xr = g_xzr[rowzr + 512 + jg];
    float xo = g_xo[rowo + jg];

    for (int t = 0; t < 2048; t++) {
        // ---------- phase A: z/r preacts, publish rg = h * sigmoid(r) ----------
        stage8(g_h, hb, b0, 0);   asm volatile("cp.async.commit_group;");
        stage8(g_h, hb, b0, 256); asm volatile("cp.async.commit_group;");

        unsigned long long az0 = 0, az1 = 0, ar0 = 0, ar1 = 0;
        asm volatile("cp.async.wait_group 1;");
        __syncthreads();
#pragma unroll 8
        for (int q = 0; q < 64; q++) {
            ulonglong2 h2 = hv[q], z2 = zv[q], r2 = rv[q];
            fma2(az0, h2.x, z2.x); fma2(az1, h2.y, z2.y);
            fma2(ar0, h2.x, r2.x); fma2(ar1, h2.y, r2.y);
        }
        asm volatile("cp.async.wait_group 0;");
        __syncthreads();
#pragma unroll 8
        for (int q = 64; q < 128; q++) {
            ulonglong2 h2 = hv[q], z2 = zv[q], r2 = rv[q];
            fma2(az0, h2.x, z2.x); fma2(az1, h2.y, z2.y);
            fma2(ar0, h2.x, r2.x); fma2(ar1, h2.y, r2.y);
        }
        float2 z0 = upk(az0), z1 = upk(az1), r0 = upk(ar0), r1 = upk(ar1);
        float az = bz + xz + z0.x + z0.y + z1.x + z1.y;
        float ar = br + xr + r0.x + r0.y + r1.x + r1.y;
        float sr = 1.f / (1.f + expf(-ar));
        st_rel(&g_rg[b * 512 + jg], myh * sr);
        float zs = 1.f / (1.f + expf(-az));
        set_flag(&g_flagA[me], t + 1);
        group_wait(g_flagA, fb, t + 1);

        // ---------- phase B: s preact, state update ----------
        stage8(g_rg, hb, b0, 0);   asm volatile("cp.async.commit_group;");
        stage8(g_rg, hb, b0, 256); asm volatile("cp.async.commit_group;");

        const float xo_cur = xo;
        // prefetch next step's input projections (overlaps B dots)
        if (t + 1 < 2048) {
            rowzr = ((size_t)b * 2048 + t + 1) * 1024;
            rowo  = ((size_t)b * 2048 + t + 1) * 512;
            xz = g_xzr[rowzr + jg];
            xr = g_xzr[rowzr + 512 + jg];
            xo = g_xo[rowo + jg];
        }

        unsigned long long ao0 = 0, ao1 = 0;
        asm volatile("cp.async.wait_group 1;");
        __syncthreads();
#pragma unroll 8
        for (int q = 0; q < 64; q++) {
            ulonglong2 h2 = hv[q], o2 = ov[q];
            fma2(ao0, h2.x, o2.x); fma2(ao1, h2.y, o2.y);
        }
        asm volatile("cp.async.wait_group 0;");
        __syncthreads();
#pragma unroll 8
        for (int q = 64; q < 128; q++) {
            ulonglong2 h2 = hv[q], o2 = ov[q];
            fma2(ao0, h2.x, o2.x); fma2(ao1, h2.y, o2.y);
        }
        float2 o0 = upk(ao0), o1 = upk(ao1);
        float as_ = bo + xo_cur + o0.x + o0.y + o1.x + o1.y;

        float hn  = (1.f - zs) * myh + zs * tanhf(as_);
        bool  act = (t < lb);
        out[((size_t)b * 2048 + t) * 512 + jg] = act ? hn : 0.f;
        if (act) myh = hn;
        st_rel(&g_h[b * 512 + jg], myh);
        set_flag(&g_flagB[me], t + 1);
        group_wait(g_flagB, fb, t + 1);
    }

    outF[b * 512 + jg] = myh;   // final_state (1,B,H)
}

// ---------------------------------------------------------------------------
extern "C" void kernel_launch(void* const* d_in, const int* in_sizes, int n_in,
                              void* d_out, int out_size)
{
    const float* seq  = (const float*)d_in[0];
    const int*   lens = (const int*)  d_in[1];
    const float* Wih  = (const float*)d_in[2];
    const float* bih  = (const float*)d_in[3];
    const float* Whh  = (const float*)d_in[4];
    const float* bhh  = (const float*)d_in[5];
    const float* Wio  = (const float*)d_in[6];
    const float* bio  = (const float*)d_in[7];
    const float* Who  = (const float*)d_in[8];
    const float* bho  = (const float*)d_in[9];
    float* out = (float*)d_out;

    const int smem = (104 * WPAD) * (int)sizeof(float);   // 214,656 B
    cudaFuncSetAttribute(gru_rec, cudaFuncAttributeMaxDynamicSharedMemorySize,
                         smem);

    dim3 grid(24, 1024);   // N tiles (16 zr + 8 o) x M tiles
    proj_gemm<<<grid, 256>>>(seq, Wih, bih, Wio, bio);
    gru_rec<<<NCTA, NTHR, smem>>>(lens, Whh, bhh, Who, bho, out);
}

// round 16
// speedup vs baseline: 1.6083x; 1.2270x over previous
#include <cuda_runtime.h>
#include <cstdint>
#include <cstddef>

// Problem: B=64, T=2048, D=512, H=512
#define NCTA 128      // 16 col-groups x 8 batch-groups
#define NTHR 256
#define WPAD 516      // padded SMEM row stride (516 % 32 == 4 -> conflict-free)

// ---------------- static device scratch (no runtime allocation) ----------------
__device__ float g_xzr[64ull * 2048 * 1024];  // [B,T,2H] input zr projection
__device__ float g_xo [64ull * 2048 * 512];   // [B,T,H]  input o  projection
__device__ float g_h  [64 * 512];             // current hidden state
__device__ float g_rg [64 * 512];             // h * sigmoid(r)
__device__ int   g_cnt   = 0;                 // init barrier
__device__ int   g_sense = 0;                 // init barrier
__device__ int   g_cA    = 0;                 // monotonic phase-A arrivals
__device__ int   g_cB    = 0;                 // monotonic phase-B arrivals

// ---------------- f32x2 packed-FMA helpers (PTX-only on sm_103a) ----------------
__device__ __forceinline__ void fma2(unsigned long long& d,
                                     unsigned long long a, unsigned long long b) {
    asm("fma.rn.f32x2 %0, %1, %2, %0;" : "+l"(d) : "l"(a), "l"(b));
}
__device__ __forceinline__ unsigned long long pk(float lo, float hi) {
    unsigned long long r;
    asm("mov.b64 %0, {%1, %2};" : "=l"(r) : "f"(lo), "f"(hi));
    return r;
}
__device__ __forceinline__ float2 upk(unsigned long long v) {
    float2 f;
    asm("mov.b64 {%0, %1}, %2;" : "=f"(f.x), "=f"(f.y) : "l"(v));
    return f;
}

// ---------------------------------------------------------------------------
// Kernel 1: fused input-projection SGEMM (f32x2 packed over k-pairs)
// ---------------------------------------------------------------------------
__global__ __launch_bounds__(256) void proj_gemm(
    const float* __restrict__ A,
    const float* __restrict__ Wih, const float* __restrict__ bih,
    const float* __restrict__ Wio, const float* __restrict__ bio)
{
    __shared__ __align__(16) float As[16][132];
    __shared__ __align__(16) float Bs[16][68];

    const int tid = threadIdx.x;
    const int n0  = blockIdx.x * 64;
    const size_t m0 = (size_t)blockIdx.y * 128;

    const float* W; const float* bias; float* out; int ldo; int nc0;
    if (n0 < 1024) { W = Wih; bias = bih; out = g_xzr; ldo = 1024; nc0 = n0; }
    else           { W = Wio; bias = bio; out = g_xo;  ldo = 512;  nc0 = n0 - 1024; }

    const int ar  = tid >> 2;
    const int ac4 = tid & 3;
    const int ty  = tid >> 4;
    const int tx  = tid & 15;

    unsigned long long acc[8][4];
#pragma unroll
    for (int i = 0; i < 8; i++)
#pragma unroll
        for (int j = 0; j < 4; j++) acc[i][j] = 0ull;

    float4 pa0 = *(const float4*)(A + (m0 + ar) * 512 + ac4 * 4);
    float4 pa1 = *(const float4*)(A + (m0 + 64 + ar) * 512 + ac4 * 4);
    float4 pb  = *(const float4*)(W + (size_t)(nc0 + ar) * 512 + ac4 * 4);

    for (int k0 = 0; k0 < 512; k0 += 16) {
        As[ac4*4+0][ar]      = pa0.x; As[ac4*4+1][ar]      = pa0.y;
        As[ac4*4+2][ar]      = pa0.z; As[ac4*4+3][ar]      = pa0.w;
        As[ac4*4+0][64 + ar] = pa1.x; As[ac4*4+1][64 + ar] = pa1.y;
        As[ac4*4+2][64 + ar] = pa1.z; As[ac4*4+3][64 + ar] = pa1.w;
        Bs[ac4*4+0][ar] = pb.x; Bs[ac4*4+1][ar] = pb.y;
        Bs[ac4*4+2][ar] = pb.z; Bs[ac4*4+3][ar] = pb.w;
        __syncthreads();

        if (k0 + 16 < 512) {
            pa0 = *(const float4*)(A + (m0 + ar) * 512 + k0 + 16 + ac4 * 4);
            pa1 = *(const float4*)(A + (m0 + 64 + ar) * 512 + k0 + 16 + ac4 * 4);
            pb  = *(const float4*)(W + (size_t)(nc0 + ar) * 512 + k0 + 16 + ac4 * 4);
        }

#pragma unroll
        for (int kp = 0; kp < 8; kp++) {
            const int kk = kp * 2;
            float4 al0 = *(const float4*)&As[kk][ty * 8];
            float4 al1 = *(const float4*)&As[kk][ty * 8 + 4];
            float4 ah0 = *(const float4*)&As[kk + 1][ty * 8];
            float4 ah1 = *(const float4*)&As[kk + 1][ty * 8 + 4];
            float4 bl  = *(const float4*)&Bs[kk][tx * 4];
            float4 bh  = *(const float4*)&Bs[kk + 1][tx * 4];
            unsigned long long pbv[4] = {
                pk(bl.x, bh.x), pk(bl.y, bh.y), pk(bl.z, bh.z), pk(bl.w, bh.w) };
            float alv[8] = {al0.x, al0.y, al0.z, al0.w, al1.x, al1.y, al1.z, al1.w};
            float ahv[8] = {ah0.x, ah0.y, ah0.z, ah0.w, ah1.x, ah1.y, ah1.z, ah1.w};
#pragma unroll
            for (int i = 0; i < 8; i++) {
                unsigned long long pav = pk(alv[i], ahv[i]);
                fma2(acc[i][0], pav, pbv[0]);
                fma2(acc[i][1], pav, pbv[1]);
                fma2(acc[i][2], pav, pbv[2]);
                fma2(acc[i][3], pav, pbv[3]);
            }
        }
        __syncthreads();
    }

    float4 bv4 = *(const float4*)(bias + nc0 + tx * 4);
#pragma unroll
    for (int i = 0; i < 8; i++) {
        float2 c0 = upk(acc[i][0]), c1 = upk(acc[i][1]);
        float2 c2 = upk(acc[i][2]), c3 = upk(acc[i][3]);
        float4 v;
        v.x = c0.x + c0.y + bv4.x; v.y = c1.x + c1.y + bv4.y;
        v.z = c2.x + c2.y + bv4.z; v.w = c3.x + c3.y + bv4.w;
        *(float4*)(out + (m0 + ty * 8 + i) * ldo + nc0 + tx * 4) = v;
    }
}

// ---------------------------------------------------------------------------
// Persistent recurrence kernel: 128 CTAs = 16 col-groups x 8 batch-groups.
// Grid sync = red.release arrive on monotonic counter + acquire poll.
// ---------------------------------------------------------------------------
__device__ __forceinline__ void st_rel(float* p, float v) {
    asm volatile("st.relaxed.gpu.global.f32 [%0], %1;" :: "l"(p), "f"(v));
}

// stage rows [b0,b0+8), cols [kbase,kbase+256) of src[64][512] -> dst[8][WPAD]
__device__ __forceinline__ void stage8(const float* __restrict__ src,
                                       float* dst, int b0, int kbase)
{
    const int t = threadIdx.x;
#pragma unroll
    for (int i = 0; i < 2; i++) {
        int idx = t + i * NTHR;
        int r   = idx >> 6;
        int q   = idx & 63;
        const float* s = src + (size_t)(b0 + r) * 512 + kbase + q * 4;
        float*       d = dst + r * WPAD + kbase + q * 4;
        unsigned sa = (unsigned)__cvta_generic_to_shared(d);
        asm volatile("cp.async.cg.shared.global [%0], [%1], 16;"
                     :: "r"(sa), "l"(s));
    }
}

// one-time grid-wide init barrier (counter+sense; runs once per launch)
__device__ __forceinline__ void init_bar(int& snc) {
    __syncthreads();
    snc ^= 1;
    if (threadIdx.x == 0) {
        int old;
        asm volatile("atom.acq_rel.gpu.global.add.s32 %0, [%1], 1;"
                     : "=r"(old) : "l"(&g_cnt) : "memory");
        if (old == NCTA - 1) {
            asm volatile("st.relaxed.gpu.global.s32 [%0], 0;"
                         :: "l"(&g_cnt) : "memory");
            asm volatile("st.release.gpu.global.s32 [%0], %1;"
                         :: "l"(&g_sense), "r"(snc) : "memory");
        }
    }
    if (threadIdx.x < 32) {
        int cur;
        do {
            asm volatile("ld.acquire.gpu.global.s32 %0, [%1];"
                         : "=r"(cur) : "l"(&g_sense) : "memory");
        } while (cur != snc);
    }
    __syncthreads();
}

// pipelined-arrive grid barrier: REDG (no-return, ~0.854 cyc/op same-addr)
// + monotonic-target acquire poll. No counter reset, no serialized RMW chain.
__device__ __forceinline__ void redbar(int* cnt, int target) {
    __syncthreads();                  // all this CTA's st.relaxed.gpu done
    if (threadIdx.x == 0)
        asm volatile("red.release.gpu.global.add.s32 [%0], %1;"
                     :: "l"(cnt), "r"(1) : "memory");
    if (threadIdx.x < 32) {
        int v;
        do {
            asm volatile("ld.acquire.gpu.global.s32 %0, [%1];"
                         : "=r"(v) : "l"(cnt) : "memory");
        } while (v < target);
    }
    __syncthreads();
}

__global__ __launch_bounds__(NTHR, 1) void gru_rec(
    const int*   __restrict__ lens,
    const float* __restrict__ Whh, const float* __restrict__ bhh,
    const float* __restrict__ Who, const float* __restrict__ bho,
    float* __restrict__ out)
{
    extern __shared__ float sm[];
    float* Wz = sm;                  // [32][WPAD]
    float* Wr = sm + 32 * WPAD;
    float* Wo = sm + 64 * WPAD;
    float* hb = sm + 96 * WPAD;      // [8][WPAD] staging (h or rg)

    const int tid  = threadIdx.x;
    const int w    = tid >> 5;
    const int lane = tid & 31;
    const int cg   = blockIdx.x >> 3;       // 0..15 column group
    const int bg   = blockIdx.x & 7;        // 0..7  batch group
    const int j_local = w * 4 + (lane & 3);
    const int b_local = lane >> 2;
    const int jg = cg * 32 + j_local;
    const int b0 = bg * 8;
    const int b  = b0 + b_local;

    int snc;
    asm volatile("ld.acquire.gpu.global.s32 %0, [%1];"
                 : "=r"(snc) : "l"(&g_sense) : "memory");

    // stage weight slices once (reused across all 2048 steps)
    for (int idx = tid; idx < 32 * 128; idx += NTHR) {
        int jj = idx >> 7, q = idx & 127;
        *(float4*)&Wz[jj * WPAD + q * 4] =
            *(const float4*)&Whh[(size_t)(cg * 32 + jj) * 512 + q * 4];
        *(float4*)&Wr[jj * WPAD + q * 4] =
            *(const float4*)&Whh[(size_t)(512 + cg * 32 + jj) * 512 + q * 4];
        *(float4*)&Wo[jj * WPAD + q * 4] =
            *(const float4*)&Who[(size_t)(cg * 32 + jj) * 512 + q * 4];
    }

    const float bz = bhh[jg], br = bhh[512 + jg], bo = bho[jg];
    const int   lb = lens[b];
    float myh = 0.f;

    // reset state; CTA 0 resets the monotonic counters (replay-safe: all
    // prior-launch pollers exited before this launch began; ordering into
    // this launch is provided by init_bar's acq_rel chain)
    st_rel(&g_h[b * 512 + jg], 0.f);
    if (blockIdx.x == 0 && tid == 0) {
        asm volatile("st.relaxed.gpu.global.s32 [%0], 0;" :: "l"(&g_cA) : "memory");
        asm volatile("st.relaxed.gpu.global.s32 [%0], 0;" :: "l"(&g_cB) : "memory");
    }
    init_bar(snc);

    float* outF = out + 64ull * 2048 * 512;   // final_state region

    const ulonglong2* zv = (const ulonglong2*)(Wz + j_local * WPAD);
    const ulonglong2* rv = (const ulonglong2*)(Wr + j_local * WPAD);
    const ulonglong2* ov = (const ulonglong2*)(Wo + j_local * WPAD);
    const ulonglong2* hv = (const ulonglong2*)(hb + b_local * WPAD);

    // prefetch step-0 input projections (streaming loads)
    size_t rowzr = ((size_t)b * 2048) * 1024;
    size_t rowo  = ((size_t)b * 2048) * 512;
    float xz = __ldcs(&g_xzr[rowzr + jg]);
    float xr = __ldcs(&g_xzr[rowzr + 512 + jg]);
    float xo = __ldcs(&g_xo[rowo + jg]);

    for (int t = 0; t < 2048; t++) {
        // ---------- phase A: z/r preacts, publish rg = h * sigmoid(r) ----------
        stage8(g_h, hb, b0, 0);
        stage8(g_h, hb, b0, 256);
        asm volatile("cp.async.commit_group;");

        unsigned long long az0 = 0, az1 = 0, ar0 = 0, ar1 = 0;
        asm volatile("cp.async.wait_group 0;");
        __syncthreads();
#pragma unroll 8
        for (int q = 0; q < 128; q++) {
            ulonglong2 h2 = hv[q], z2 = zv[q], r2 = rv[q];
            fma2(az0, h2.x, z2.x); fma2(az1, h2.y, z2.y);
            fma2(ar0, h2.x, r2.x); fma2(ar1, h2.y, r2.y);
        }
        float2 z0 = upk(az0), z1 = upk(az1), r0 = upk(ar0), r1 = upk(ar1);
        float az = bz + xz + z0.x + z0.y + z1.x + z1.y;
        float ar = br + xr + r0.x + r0.y + r1.x + r1.y;
        float sr = 1.f / (1.f + expf(-ar));
        st_rel(&g_rg[b * 512 + jg], myh * sr);
        float zs = 1.f / (1.f + expf(-az));
        redbar(&g_cA, NCTA * (t + 1));

        // ---------- phase B: s preact, state update ----------
        stage8(g_rg, hb, b0, 0);
        stage8(g_rg, hb, b0, 256);
        asm volatile("cp.async.commit_group;");

        const float xo_cur = xo;
        if (t + 1 < 2048) {            // prefetch next step (overlaps B dot)
            rowzr = ((size_t)b * 2048 + t + 1) * 1024;
            rowo  = ((size_t)b * 2048 + t + 1) * 512;
            xz = __ldcs(&g_xzr[rowzr + jg]);
            xr = __ldcs(&g_xzr[rowzr + 512 + jg]);
            xo = __ldcs(&g_xo[rowo + jg]);
        }

        unsigned long long ao0 = 0, ao1 = 0;
        asm volatile("cp.async.wait_group 0;");
        __syncthreads();
#pragma unroll 8
        for (int q = 0; q < 128; q++) {
            ulonglong2 h2 = hv[q], o2 = ov[q];
            fma2(ao0, h2.x, o2.x); fma2(ao1, h2.y, o2.y);
        }
        float2 o0 = upk(ao0), o1 = upk(ao1);
        float as_ = bo + xo_cur + o0.x + o0.y + o1.x + o1.y;

        float hn  = (1.f - zs) * myh + zs * tanhf(as_);
        bool  act = (t < lb);
        __stcs(&out[((size_t)b * 2048 + t) * 512 + jg], act ? hn : 0.f);
        if (act) myh = hn;
        st_rel(&g_h[b * 512 + jg], myh);
        redbar(&g_cB, NCTA * (t + 1));
    }

    outF[b * 512 + jg] = myh;   // final_state (1,B,H)
}

// ---------------------------------------------------------------------------
extern "C" void kernel_launch(void* const* d_in, const int* in_sizes, int n_in,
                              void* d_out, int out_size)
{
    const float* seq  = (const float*)d_in[0];
    const int*   lens = (const int*)  d_in[1];
    const float* Wih  = (const float*)d_in[2];
    const float* bih  = (const float*)d_in[3];
    const float* Whh  = (const float*)d_in[4];
    const float* bhh  = (const float*)d_in[5];
    const float* Wio  = (const float*)d_in[6];
    const float* bio  = (const float*)d_in[7];
    const float* Who  = (const float*)d_in[8];
    const float* bho  = (const float*)d_in[9];
    float* out = (float*)d_out;

    const int smem = (104 * WPAD) * (int)sizeof(float);   // 214,656 B
    cudaFuncSetAttribute(gru_rec, cudaFuncAttributeMaxDynamicSharedMemorySize,
                         smem);

    dim3 grid(24, 1024);   // N tiles (16 zr + 8 o) x M tiles
    proj_gemm<<<grid, 256>>>(seq, Wih, bih, Wio, bio);
    gru_rec<<<NCTA, NTHR, smem>>>(lens, Whh, bhh, Who, bho, out);
}